// round 15
// baseline (speedup 1.0000x reference)
#include <cuda_runtime.h>

typedef unsigned long long u64;

#define NQ    12
#define DEPTH 4
#define NPAR  144
#define THREADS 256

// ---------- f32x2 packed helpers ----------
__device__ __forceinline__ u64 f2fma(u64 a, u64 b, u64 c) {
    u64 d; asm("fma.rn.f32x2 %0,%1,%2,%3;" : "=l"(d) : "l"(a), "l"(b), "l"(c)); return d;
}
__device__ __forceinline__ u64 f2mul(u64 a, u64 b) {
    u64 d; asm("mul.rn.f32x2 %0,%1,%2;" : "=l"(d) : "l"(a), "l"(b)); return d;
}
__device__ __forceinline__ u64 pk(float lo, float hi) {
    u64 r; asm("mov.b64 %0,{%1,%2};" : "=l"(r) : "f"(lo), "f"(hi)); return r;
}
__device__ __forceinline__ void upk(u64 v, float& lo, float& hi) {
    asm("mov.b64 {%0,%1},%2;" : "=f"(lo), "=f"(hi) : "l"(v));
}
__device__ __forceinline__ u64 f2swap(u64 v) {
    float lo, hi; upk(v, lo, hi); return pk(hi, lo);
}

struct c2 { float r, i; };
__device__ __forceinline__ c2 cmul(c2 a, c2 b) {
    c2 o; o.r = a.r * b.r - a.i * b.i; o.i = a.r * b.i + a.i * b.r; return o;
}
__device__ __forceinline__ float2 cm2(float2 a, float2 b) {
    return make_float2(a.x * b.x - a.y * b.y, a.x * b.y + a.y * b.x);
}

// ---------- CNOT-ring permutation (reference gate order) ----------
__device__ __forceinline__ int perm12(int s) {
    int d = s;
    #pragma unroll
    for (int q = 0; q < 12; q++) {
        int bc = 11 - q, bt = 11 - ((q + 1) % 12);
        d ^= ((d >> bc) & 1) << bt;
    }
    return d;
}
__device__ __forceinline__ int laddr(int d) {
    return ((d >> 5) << 7) | ((((d >> 1) & 15) ^ ((d >> 5) & 15)) << 3) | ((d & 1) << 2);
}
__device__ __forceinline__ int bmoff(int m) {
    return (m << 10) | ((m & 1) << 6);
}

// ---------- real-core gate macros (G = [[ra, rb],[-rb, ra]]) ----------
#define LOADG(gi)                                                     \
    ulonglong2 g01 = *(const ulonglong2*)(gpkG + (gi) * 4);           \
    ulonglong2 g23 = *(const ulonglong2*)(gpkG + (gi) * 4 + 2);       \
    u64 RA = g01.x, RB = g01.y, RBm = g23.x, RBpm = g23.y;

#define PACKG(gi)                                                     \
    {                                                                 \
        LOADG(gi)                                                     \
        (void)RB; (void)RBm;                                          \
        _Pragma("unroll")                                             \
        for (int p = 0; p < 8; p++) {                                 \
            u64 R = Re[p], I = Im[p];                                 \
            Re[p] = f2fma(RBpm, f2swap(R), f2mul(RA, R));             \
            Im[p] = f2fma(RBpm, f2swap(I), f2mul(RA, I));             \
        }                                                             \
    }

#define REGPG(gi, mask)                                               \
    {                                                                 \
        LOADG(gi)                                                     \
        (void)RBpm;                                                   \
        _Pragma("unroll")                                             \
        for (int p0 = 0; p0 < 8; p0++) {                              \
            if (p0 & (mask)) continue;                                \
            const int p1 = p0 | (mask);                               \
            u64 aR = Re[p0], aI = Im[p0], bR = Re[p1], bI = Im[p1];   \
            Re[p0] = f2fma(RB, bR, f2mul(RA, aR));                    \
            Im[p0] = f2fma(RB, bI, f2mul(RA, aI));                    \
            Re[p1] = f2fma(RBm, aR, f2mul(RA, bR));                   \
            Im[p1] = f2fma(RBm, aI, f2mul(RA, bI));                   \
        }                                                             \
    }

#define SHUFG(gi, lm, mybit)                                          \
    {                                                                 \
        LOADG(gi)                                                     \
        (void)RBpm;                                                   \
        u64 Yo = (mybit) ? RBm : RB;                                  \
        _Pragma("unroll")                                             \
        for (int p = 0; p < 8; p++) {                                 \
            u64 mR = Re[p], mI = Im[p];                               \
            u64 oR = __shfl_xor_sync(0xffffffffu, mR, lm);            \
            u64 oI = __shfl_xor_sync(0xffffffffu, mI, lm);            \
            Re[p] = f2fma(Yo, oR, f2mul(RA, mR));                     \
            Im[p] = f2fma(Yo, oI, f2mul(RA, mI));                     \
        }                                                             \
    }

// diagonal passes
#define APPLY_SCALAR(sv)                                              \
    {                                                                 \
        u64 SX = pk((sv).x, (sv).x);                                  \
        u64 SY = pk((sv).y, (sv).y);                                  \
        u64 SYm = pk(-(sv).y, -(sv).y);                               \
        _Pragma("unroll")                                             \
        for (int p = 0; p < 8; p++) {                                 \
            u64 R = Re[p], I = Im[p];                                 \
            Re[p] = f2fma(SYm, I, f2mul(SX, R));                      \
            Im[p] = f2fma(SY, R, f2mul(SX, I));                       \
        }                                                             \
    }

#define APPLY_TAB(tabname, li)                                        \
    {                                                                 \
        _Pragma("unroll")                                             \
        for (int p = 0; p < 8; p++) {                                 \
            ulonglong2 dd = *(const ulonglong2*)&tabname[li][p][0];   \
            u64 DR = dd.x, DI = dd.y, DNI = tabname[li][p][2];        \
            u64 R = Re[p], I = Im[p];                                 \
            Re[p] = f2fma(DNI, I, f2mul(DR, R));                      \
            Im[p] = f2fma(DI, R, f2mul(DR, I));                       \
        }                                                             \
    }

// one full layer body (LL = layer index, compile-time).
// No pre-transpose barrier: transpose store slots are self-owned (bijective
// (t,p)->unit map; same thread last read them in the previous perm-load).
// For LAST layer: L_A(LL) scalar dropped (diagonal before |.|^2 measurement).
#define LAYER_BODY(LL, LAST)                                          \
    {                                                                 \
        PACKG((LL) * 12 + 11)                                         \
        REGPG((LL) * 12 + 10, 1)                                      \
        REGPG((LL) * 12 + 9, 2)                                       \
        REGPG((LL) * 12 + 8, 4)                                       \
        SHUFG((LL) * 12 + 7, 1, t & 1)                                \
        SHUFG((LL) * 12 + 6, 2, (t >> 1) & 1)                         \
        SHUFG((LL) * 12 + 5, 4, (t >> 2) & 1)                         \
        SHUFG((LL) * 12 + 4, 8, (t >> 3) & 1)                         \
        _Pragma("unroll")                                             \
        for (int p = 0; p < 8; p++) {                                 \
            exR64[AbU ^ p] = Re[p];                                   \
            exI64[AbU ^ p] = Im[p];                                   \
        }                                                             \
        __syncthreads();                                              \
        _Pragma("unroll")                                             \
        for (int pB = 0; pB < 8; pB++) {                              \
            const int a0 = Bb ^ bmoff(2 * pB);                        \
            const int a1 = Bb ^ bmoff(2 * pB + 1);                    \
            float r0 = *(const float*)((const char*)exR + a0);        \
            float r1 = *(const float*)((const char*)exR + a1);        \
            float i0 = *(const float*)((const char*)exI + a0);        \
            float i1 = *(const float*)((const char*)exI + a1);        \
            Re[pB] = pk(r0, r1);                                      \
            Im[pB] = pk(i0, i1);                                      \
        }                                                             \
        if (!(LAST)) {                                                \
            float2 ts1 = TS1t[((LL) - 1) & 1][t];                     \
            APPLY_SCALAR(ts1)                                         \
        }                                                             \
        APPLY_TAB(LP1t, (LL))                                         \
        PACKG((LL) * 12 + 3)                                          \
        REGPG((LL) * 12 + 2, 1)                                       \
        REGPG((LL) * 12 + 1, 2)                                       \
        REGPG((LL) * 12 + 0, 4)                                       \
        if (!(LAST)) {                                                \
            __syncthreads();                                          \
            _Pragma("unroll")                                         \
            for (int pB = 0; pB < 8; pB++) {                          \
                ulonglong2 dd = *(const ulonglong2*)&LP2t[(LL)][pB][0]; \
                u64 DR = dd.x, DI = dd.y, DNI = LP2t[(LL)][pB][2];    \
                u64 R = Re[pB], I = Im[pB];                           \
                u64 Rn = f2fma(DNI, I, f2mul(DR, R));                 \
                u64 In = f2fma(DI, R, f2mul(DR, I));                  \
                float r0, r1, i0v, i1v;                               \
                upk(Rn, r0, r1);                                      \
                upk(In, i0v, i1v);                                    \
                const int a0 = puA ^ laddr(perm12((2 * pB) << 8));    \
                const int a1 = puA ^ laddr(perm12((2 * pB + 1) << 8)); \
                *(float*)((char*)exR + a0) = r0;                      \
                *(float*)((char*)exI + a0) = i0v;                     \
                *(float*)((char*)exR + a1) = r1;                      \
                *(float*)((char*)exI + a1) = i1v;                     \
            }                                                         \
            __syncthreads();                                          \
            _Pragma("unroll")                                         \
            for (int p = 0; p < 8; p++) {                             \
                Re[p] = exR64[AbU ^ p];                               \
                Im[p] = exI64[AbU ^ p];                               \
            }                                                         \
            {                                                         \
                float2 ts2 = TS2t[(LL) + 1][t & 15];                  \
                APPLY_SCALAR(ts2)                                     \
                APPLY_TAB(LPAt, (LL) + 1)                             \
            }                                                         \
        }                                                             \
    }

__global__ __launch_bounds__(THREADS, 2)
void qgen_kernel(const float* __restrict__ noise,
                 const float* __restrict__ W1, const float* __restrict__ b1,
                 const float* __restrict__ W2, const float* __restrict__ b2,
                 const float* __restrict__ W3, const float* __restrict__ b3,
                 const float* __restrict__ W4, const float* __restrict__ b4,
                 float* __restrict__ out)
{
    __shared__ __align__(16) float exR[4096];
    __shared__ __align__(16) float exI[4096];
    __shared__ __align__(16) u64   gpkG[48 * 4];   // RA, RB, RBm, RBpm per gate
    __shared__ float2 s_rho[48];                   // right phase (on bit=1)
    __shared__ float2 s_lam[48];                   // left phase (on bit=1)
    __shared__ __align__(16) u64 LP1t[4][8][4];    // Δ1 local (ρ of B gates)
    __shared__ __align__(16) u64 LP2t[4][8][4];    // L_B local (λ of B gates)
    __shared__ __align__(16) u64 LPAt[4][8][4];    // R_A local (ρ of q11..q8)
    __shared__ float2 TS1t[2][256];                // Δ1 thread part (λ of A gates), l=1,2
    __shared__ float2 TS2t[4][16];                 // R_A thread part (ρ of q7..q4)
    __shared__ float2 s_sc[NPAR];                  // (sin, cos) of 0.5*param
    __shared__ float2 s_v[12][2];
    __shared__ float s_nz[12];
    __shared__ float s_h[64];
    __shared__ float s_meas[12];
    __shared__ float s_wsum[8][12];
    __shared__ float s_h2[64];

    const int t   = threadIdx.x;
    const int bId = blockIdx.x;

    if (t < 12) s_nz[t] = noise[bId * 12 + t];
    __syncthreads();

    // ---- MLP1 ----
    if (t < 64) {
        float acc = b1[t];
        #pragma unroll
        for (int m = 0; m < 12; m++) acc += s_nz[m] * W1[m * 64 + t];
        s_h[t] = tanhf(acc);
    }
    __syncthreads();

    // ---- MLP2 (4-way ILP) + per-param sincos (own value, no extra barrier) ----
    if (t < NPAR) {
        float a0 = b2[t], a1 = 0.f, a2 = 0.f, a3 = 0.f;
        #pragma unroll 4
        for (int j = 0; j < 64; j += 4) {
            a0 += s_h[j + 0] * W2[(j + 0) * NPAR + t];
            a1 += s_h[j + 1] * W2[(j + 1) * NPAR + t];
            a2 += s_h[j + 2] * W2[(j + 2) * NPAR + t];
            a3 += s_h[j + 3] * W2[(j + 3) * NPAR + t];
        }
        float v = (a0 + a1) + (a2 + a3);
        float sv, cv;
        sincosf(0.5f * v, &sv, &cv);
        s_sc[t] = make_float2(sv, cv);
    }
    __syncthreads();

    // ---- per-gate: U = RZ RY RX = [[a,b],[-b*,a*]], a=gx+igy, b=gz+igw.
    // U ~ diag(1, conj(c)conj(d)) * [[ra,rb],[-rb,ra]] * diag(1, d*conj(c))
    if (t < 48) {
        float2 A  = s_sc[t * 3 + 0];
        float2 Bv = s_sc[t * 3 + 1];
        float2 Cv = s_sc[t * 3 + 2];
        float sa = A.x,  ca = A.y;
        float sb = Bv.x, cb = Bv.y;
        float sc = Cv.x, cc = Cv.y;
        float x = cb * ca, y = sb * sa, z = sb * ca, w = cb * sa;
        float gx =  cc * x + sc * y;
        float gy =  cc * y - sc * x;
        float gz = -(cc * z + sc * w);
        float gw =  sc * z - cc * w;

        float ra = sqrtf(gx * gx + gy * gy);
        float rb = sqrtf(gz * gz + gw * gw);
        float cx, cyv, dx, dyv;
        if (ra > 1e-30f) { cx = gx / ra; cyv = gy / ra; } else { cx = 1.f; cyv = 0.f; }
        if (rb > 1e-30f) { dx = gz / rb; dyv = gw / rb; } else { dx = 1.f; dyv = 0.f; }

        s_rho[t] = make_float2(dx * cx + dyv * cyv, dyv * cx - dx * cyv);
        s_lam[t] = make_float2(cx * dx - cyv * dyv, -(cx * dyv + cyv * dx));

        u64* r = gpkG + t * 4;
        r[0] = pk(ra, ra);
        r[1] = pk(rb, rb);
        r[2] = pk(-rb, -rb);
        r[3] = pk(rb, -rb);

        if (t < 12) {
            s_v[t][0] = make_float2(gx, gy);
            s_v[t][1] = make_float2(-gz, gw);
        }
    }
    __syncthreads();

    // ---- build diagonal tables ----
    #pragma unroll
    for (int l = 1; l <= 2; l++) {     // L_A(3) dropped (phase-only before meas)
        float2 acc = make_float2(1.f, 0.f);
        #pragma unroll
        for (int b = 0; b < 8; b++)
            if ((t >> b) & 1) acc = cm2(acc, s_lam[l * 12 + (11 - b)]);
        TS1t[l - 1][t] = acc;
    }
    if (t < 48) {
        int l = (t >> 4) + 1, u = t & 15;
        float2 acc = make_float2(1.f, 0.f);
        #pragma unroll
        for (int j = 0; j < 4; j++)
            if ((u >> j) & 1) acc = cm2(acc, s_rho[l * 12 + (7 - j)]);
        TS2t[l][u] = acc;
    }
    if (t < 24) {
        int l = t / 8 + 1, r = t % 8;
        {
            float2 b0 = make_float2(1.f, 0.f);
            if (r & 1) b0 = cm2(b0, s_rho[l * 12 + 2]);
            if (r & 2) b0 = cm2(b0, s_rho[l * 12 + 1]);
            if (r & 4) b0 = cm2(b0, s_rho[l * 12 + 0]);
            float2 b1v = cm2(b0, s_rho[l * 12 + 3]);
            LP1t[l][r][0] = pk(b0.x, b1v.x);
            LP1t[l][r][1] = pk(b0.y, b1v.y);
            LP1t[l][r][2] = pk(-b0.y, -b1v.y);
        }
        {
            float2 b0 = make_float2(1.f, 0.f);
            if (r & 1) b0 = cm2(b0, s_rho[l * 12 + 10]);
            if (r & 2) b0 = cm2(b0, s_rho[l * 12 + 9]);
            if (r & 4) b0 = cm2(b0, s_rho[l * 12 + 8]);
            float2 b1v = cm2(b0, s_rho[l * 12 + 11]);
            LPAt[l][r][0] = pk(b0.x, b1v.x);
            LPAt[l][r][1] = pk(b0.y, b1v.y);
            LPAt[l][r][2] = pk(-b0.y, -b1v.y);
        }
    }
    if (t < 16) {
        int l = t / 8 + 1, r = t % 8;
        float2 b0 = make_float2(1.f, 0.f);
        if (r & 1) b0 = cm2(b0, s_lam[l * 12 + 2]);
        if (r & 2) b0 = cm2(b0, s_lam[l * 12 + 1]);
        if (r & 4) b0 = cm2(b0, s_lam[l * 12 + 0]);
        float2 b1v = cm2(b0, s_lam[l * 12 + 3]);
        LP2t[l][r][0] = pk(b0.x, b1v.x);
        LP2t[l][r][1] = pk(b0.y, b1v.y);
        LP2t[l][r][2] = pk(-b0.y, -b1v.y);
    }

    // ---- per-thread exchange addresses ----
    const int AbU = ((t >> 1) << 4) | (((t & 1) << 3) ^ ((t >> 1) & 15));
    const int uh  = t >> 5;
    const int Bb  = (uh << 7) | ((((t >> 1) & 15) ^ uh) << 3) | ((t & 1) << 2);
    const int puA = laddr(perm12(t));

    u64* exR64 = (u64*)exR;
    u64* exI64 = (u64*)exI;

    __syncthreads();   // tables + gpkG + s_v visible

    // ---- layer 0 (gates + first ring) via product-state synthesis ----
    u64 Re[8], Im[8];
    {
        c2 v[12][2];
        #pragma unroll
        for (int q = 0; q < 12; q++) {
            float2 a0 = s_v[q][0], a1 = s_v[q][1];
            v[q][0].r = a0.x; v[q][0].i = a0.y;
            v[q][1].r = a1.x; v[q][1].i = a1.y;
        }
        const int x2 = ((t >> 5) ^ (t >> 6)) & 1;
        const int x3 = ((t >> 4) ^ (t >> 5)) & 1;
        const int x4 = ((t >> 3) ^ (t >> 4)) & 1;
        const int x5 = ((t >> 2) ^ (t >> 3)) & 1;
        const int x6 = ((t >> 1) ^ (t >> 2)) & 1;
        const int x7 = ( t       ^ (t >> 1)) & 1;
        const int e0 = (t >> 7) & 1;
        const int e1 = ((t >> 6) ^ (t >> 7)) & 1;
        const int e4 = t & 1;

        c2 base = cmul(cmul(cmul(v[2][x2], v[3][x3]), cmul(v[4][x4], v[5][x5])),
                       cmul(v[6][x6], v[7][x7]));
        c2 base2[2];
        base2[0] = cmul(base, v[8][e4]);
        base2[1] = cmul(base, v[8][e4 ^ 1]);

        c2 A[2];
        A[0] = cmul(v[0][e0],     v[1][e1]);
        A[1] = cmul(v[0][e0 ^ 1], v[1][e1 ^ 1]);
        c2 B[4];
        B[0] = cmul(A[0], v[11][0]);
        B[1] = cmul(A[1], v[11][1]);
        B[2] = cmul(A[0], v[11][1]);
        B[3] = cmul(A[1], v[11][0]);
        c2 C[8];
        #pragma unroll
        for (int k2 = 0; k2 < 2; k2++)
            #pragma unroll
            for (int j = 0; j < 4; j++)
                C[k2 * 4 + j] = cmul(B[j], v[10][((j >> 1) & 1) ^ k2]);
        #pragma unroll
        for (int k3 = 0; k3 < 2; k3++)
            #pragma unroll
            for (int j = 0; j < 8; j += 2) {
                c2 d0 = cmul(cmul(C[j],     v[9][((j >> 2) & 1) ^ k3]), base2[k3]);
                c2 d1 = cmul(cmul(C[j + 1], v[9][(((j+1) >> 2) & 1) ^ k3]), base2[k3]);
                int p = (k3 * 8 + j) >> 1;
                Re[p] = pk(d0.r, d1.r);
                Im[p] = pk(d0.i, d1.i);
            }
    }

    // R_A(1): right phases of layer-1 A gates (post-synthesis, layout A)
    {
        float2 ts2 = TS2t[1][t & 15];
        APPLY_SCALAR(ts2)
        APPLY_TAB(LPAt, 1)
    }

    // ---- layers 1..3 (fully unrolled) ----
    LAYER_BODY(1, false)
    LAYER_BODY(2, false)
    LAYER_BODY(3, true)

    // ---- <Z_q> in layout B with post-ring prefix-parity signs ----
    float T0 = 0.f, T1 = 0.f, T2 = 0.f, T3 = 0.f;
    #pragma unroll
    for (int pB = 0; pB < 8; pB++) {
        u64 p2 = f2fma(Im[pB], Im[pB], f2mul(Re[pB], Re[pB]));
        float pl, ph; upk(p2, pl, ph);
        float sm = pl + ph, df = pl - ph;
        T0 += (__popc(pB & 3) & 1) ? -df : df;
        T1 += (__popc(pB & 6) & 1) ? -sm : sm;
        T2 += (__popc(pB & 7) & 1) ? -sm : sm;
        T3 += (__popc(pB & 7) & 1) ? -df : df;
    }

    // ---- Walsh-tree lane reductions (30 SHFL instead of 60) ----
    // Lane masks: c0:T0@0x1F; c1:T1 plain; c2:T2 plain; c3..c6:T3 plain;
    // c7..c11: T3 @ {0x10,0x18,0x1C,0x1E,0x1F}. Warp-bit signs applied at write.
    const unsigned FM = 0xffffffffu;
    float o;
    // T3 shared prefix tree
    o = __shfl_xor_sync(FM, T3, 1);
    float tP = T3 + o;
    float t1f = (t & 1) ? (o - T3) : (T3 - o);
    o = __shfl_xor_sync(FM, tP, 2);
    float tP1 = tP + o;
    float t1e = ((t >> 1) & 1) ? (o - tP) : (tP - o);
    o = __shfl_xor_sync(FM, t1f, 2);
    t1f = ((t >> 1) & 1) ? (o - t1f) : (t1f - o);
    o = __shfl_xor_sync(FM, tP1, 4);
    float tP2 = tP1 + o;
    float t1c = ((t >> 2) & 1) ? (o - tP1) : (tP1 - o);
    o = __shfl_xor_sync(FM, t1e, 4);
    t1e = ((t >> 2) & 1) ? (o - t1e) : (t1e - o);
    o = __shfl_xor_sync(FM, t1f, 4);
    t1f = ((t >> 2) & 1) ? (o - t1f) : (t1f - o);
    o = __shfl_xor_sync(FM, tP2, 8);
    float tP3 = tP2 + o;
    float t18 = ((t >> 3) & 1) ? (o - tP2) : (tP2 - o);
    o = __shfl_xor_sync(FM, t1c, 8);
    t1c = ((t >> 3) & 1) ? (o - t1c) : (t1c - o);
    o = __shfl_xor_sync(FM, t1e, 8);
    t1e = ((t >> 3) & 1) ? (o - t1e) : (t1e - o);
    o = __shfl_xor_sync(FM, t1f, 8);
    t1f = ((t >> 3) & 1) ? (o - t1f) : (t1f - o);
    o = __shfl_xor_sync(FM, tP3, 16);
    float tPlain = tP3 + o;
    float t10 = ((t >> 4) & 1) ? (o - tP3) : (tP3 - o);
    o = __shfl_xor_sync(FM, t18, 16);
    t18 = ((t >> 4) & 1) ? (o - t18) : (t18 - o);
    o = __shfl_xor_sync(FM, t1c, 16);
    t1c = ((t >> 4) & 1) ? (o - t1c) : (t1c - o);
    o = __shfl_xor_sync(FM, t1e, 16);
    t1e = ((t >> 4) & 1) ? (o - t1e) : (t1e - o);
    o = __shfl_xor_sync(FM, t1f, 16);
    t1f = ((t >> 4) & 1) ? (o - t1f) : (t1f - o);
    // T0 full-signed, T1/T2 plain
    float u0 = T0, u1 = T1, u2 = T2;
    #pragma unroll
    for (int b = 0; b < 5; b++) {
        float oo = __shfl_xor_sync(FM, u0, 1 << b);
        u0 = ((t >> b) & 1) ? (oo - u0) : (u0 - oo);
        u1 += __shfl_xor_sync(FM, u1, 1 << b);
        u2 += __shfl_xor_sync(FM, u2, 1 << b);
    }

    const int warp = t >> 5, lane = t & 31;
    if (lane == 0) {
        // warp bits: w0=t5, w1=t6, w2=t7. Masks: 0x80->w&4, 0xC0->w&6, 0xE0->w&7
        const float sE = (__popc(warp & 7) & 1) ? -1.f : 1.f;
        const float sC = (__popc(warp & 6) & 1) ? -1.f : 1.f;
        const float s8 = (warp & 4) ? -1.f : 1.f;
        s_wsum[warp][0]  = sE * u0;
        s_wsum[warp][1]  = u1;
        s_wsum[warp][2]  = u2;
        s_wsum[warp][3]  = tPlain;
        s_wsum[warp][4]  = s8 * tPlain;
        s_wsum[warp][5]  = sC * tPlain;
        s_wsum[warp][6]  = sE * tPlain;
        s_wsum[warp][7]  = sE * t10;
        s_wsum[warp][8]  = sE * t18;
        s_wsum[warp][9]  = sE * t1c;
        s_wsum[warp][10] = sE * t1e;
        s_wsum[warp][11] = sE * t1f;
    }
    __syncthreads();
    if (t < 12) {
        float m = 0.f;
        #pragma unroll
        for (int w = 0; w < 8; w++) m += s_wsum[w][t];
        s_meas[t] = m;
    }
    __syncthreads();

    // ---- MLP3 ----
    if (t < 64) {
        float acc = b3[t];
        #pragma unroll
        for (int q = 0; q < 12; q++) acc += s_meas[q] * W3[q * 64 + t];
        s_h2[t] = tanhf(acc);
    }
    __syncthreads();

    // ---- out: 32 threads, warp-parallel reduction ----
    if (t < 32) {
        float p0 = s_h2[t] * W4[t * 2 + 0] + s_h2[t + 32] * W4[(t + 32) * 2 + 0];
        float p1 = s_h2[t] * W4[t * 2 + 1] + s_h2[t + 32] * W4[(t + 32) * 2 + 1];
        #pragma unroll
        for (int s = 16; s >= 1; s >>= 1) {
            p0 += __shfl_xor_sync(0xffffffffu, p0, s);
            p1 += __shfl_xor_sync(0xffffffffu, p1, s);
        }
        if (t == 0) {
            out[bId * 2 + 0] = p0 + b4[0];
            out[bId * 2 + 1] = p1 + b4[1];
        }
    }
}

extern "C" void kernel_launch(void* const* d_in, const int* in_sizes, int n_in,
                              void* d_out, int out_size)
{
    (void)n_in; (void)out_size;
    const float* noise = (const float*)d_in[0];
    const float* W1    = (const float*)d_in[1];
    const float* b1    = (const float*)d_in[2];
    const float* W2    = (const float*)d_in[3];
    const float* b2    = (const float*)d_in[4];
    const float* W3    = (const float*)d_in[5];
    const float* b3    = (const float*)d_in[6];
    const float* W4    = (const float*)d_in[7];
    const float* b4    = (const float*)d_in[8];
    float* out = (float*)d_out;

    const int B = in_sizes[0] / NQ;
    qgen_kernel<<<B, THREADS>>>(noise, W1, b1, W2, b2, W3, b3, W4, b4, out);
}

// round 16
// speedup vs baseline: 1.0435x; 1.0435x over previous
#include <cuda_runtime.h>

typedef unsigned long long u64;

#define NQ    12
#define DEPTH 4
#define NPAR  144
#define THREADS 256

// ---------- f32x2 packed helpers ----------
__device__ __forceinline__ u64 f2fma(u64 a, u64 b, u64 c) {
    u64 d; asm("fma.rn.f32x2 %0,%1,%2,%3;" : "=l"(d) : "l"(a), "l"(b), "l"(c)); return d;
}
__device__ __forceinline__ u64 f2mul(u64 a, u64 b) {
    u64 d; asm("mul.rn.f32x2 %0,%1,%2;" : "=l"(d) : "l"(a), "l"(b)); return d;
}
__device__ __forceinline__ u64 pk(float lo, float hi) {
    u64 r; asm("mov.b64 %0,{%1,%2};" : "=l"(r) : "f"(lo), "f"(hi)); return r;
}
__device__ __forceinline__ void upk(u64 v, float& lo, float& hi) {
    asm("mov.b64 {%0,%1},%2;" : "=f"(lo), "=f"(hi) : "l"(v));
}
__device__ __forceinline__ u64 f2swap(u64 v) {
    float lo, hi; upk(v, lo, hi); return pk(hi, lo);
}

struct c2 { float r, i; };
__device__ __forceinline__ c2 cmul(c2 a, c2 b) {
    c2 o; o.r = a.r * b.r - a.i * b.i; o.i = a.r * b.i + a.i * b.r; return o;
}
__device__ __forceinline__ float2 cm2(float2 a, float2 b) {
    return make_float2(a.x * b.x - a.y * b.y, a.x * b.y + a.y * b.x);
}

// ---------- CNOT-ring permutation (reference gate order) ----------
__device__ __forceinline__ int perm12(int s) {
    int d = s;
    #pragma unroll
    for (int q = 0; q < 12; q++) {
        int bc = 11 - q, bt = 11 - ((q + 1) % 12);
        d ^= ((d >> bc) & 1) << bt;
    }
    return d;
}
__device__ __forceinline__ int laddr(int d) {
    return ((d >> 5) << 7) | ((((d >> 1) & 15) ^ ((d >> 5) & 15)) << 3) | ((d & 1) << 2);
}
__device__ __forceinline__ int bmoff(int m) {
    return (m << 10) | ((m & 1) << 6);
}

// ---------- real-core gate macros (G = [[ra, rb],[-rb, ra]]) ----------
#define LOADG(gi)                                                     \
    ulonglong2 g01 = *(const ulonglong2*)(gpkG + (gi) * 4);           \
    ulonglong2 g23 = *(const ulonglong2*)(gpkG + (gi) * 4 + 2);       \
    u64 RA = g01.x, RB = g01.y, RBm = g23.x, RBpm = g23.y;

#define PACKG(gi)                                                     \
    {                                                                 \
        LOADG(gi)                                                     \
        (void)RB; (void)RBm;                                          \
        _Pragma("unroll")                                             \
        for (int p = 0; p < 8; p++) {                                 \
            u64 R = Re[p], I = Im[p];                                 \
            Re[p] = f2fma(RBpm, f2swap(R), f2mul(RA, R));             \
            Im[p] = f2fma(RBpm, f2swap(I), f2mul(RA, I));             \
        }                                                             \
    }

#define REGPG(gi, mask)                                               \
    {                                                                 \
        LOADG(gi)                                                     \
        (void)RBpm;                                                   \
        _Pragma("unroll")                                             \
        for (int p0 = 0; p0 < 8; p0++) {                              \
            if (p0 & (mask)) continue;                                \
            const int p1 = p0 | (mask);                               \
            u64 aR = Re[p0], aI = Im[p0], bR = Re[p1], bI = Im[p1];   \
            Re[p0] = f2fma(RB, bR, f2mul(RA, aR));                    \
            Im[p0] = f2fma(RB, bI, f2mul(RA, aI));                    \
            Re[p1] = f2fma(RBm, aR, f2mul(RA, bR));                   \
            Im[p1] = f2fma(RBm, aI, f2mul(RA, bI));                   \
        }                                                             \
    }

#define SHUFG(gi, lm, mybit)                                          \
    {                                                                 \
        LOADG(gi)                                                     \
        (void)RBpm;                                                   \
        u64 Yo = (mybit) ? RBm : RB;                                  \
        _Pragma("unroll")                                             \
        for (int p = 0; p < 8; p++) {                                 \
            u64 mR = Re[p], mI = Im[p];                               \
            u64 oR = __shfl_xor_sync(0xffffffffu, mR, lm);            \
            u64 oI = __shfl_xor_sync(0xffffffffu, mI, lm);            \
            Re[p] = f2fma(Yo, oR, f2mul(RA, mR));                     \
            Im[p] = f2fma(Yo, oI, f2mul(RA, mI));                     \
        }                                                             \
    }

// diagonal passes
#define APPLY_SCALAR(sv)                                              \
    {                                                                 \
        u64 SX = pk((sv).x, (sv).x);                                  \
        u64 SY = pk((sv).y, (sv).y);                                  \
        u64 SYm = pk(-(sv).y, -(sv).y);                               \
        _Pragma("unroll")                                             \
        for (int p = 0; p < 8; p++) {                                 \
            u64 R = Re[p], I = Im[p];                                 \
            Re[p] = f2fma(SYm, I, f2mul(SX, R));                      \
            Im[p] = f2fma(SY, R, f2mul(SX, I));                       \
        }                                                             \
    }

#define APPLY_TAB(tabname, li)                                        \
    {                                                                 \
        _Pragma("unroll")                                             \
        for (int p = 0; p < 8; p++) {                                 \
            ulonglong2 dd = *(const ulonglong2*)&tabname[li][p][0];   \
            u64 DR = dd.x, DI = dd.y, DNI = tabname[li][p][2];        \
            u64 R = Re[p], I = Im[p];                                 \
            Re[p] = f2fma(DNI, I, f2mul(DR, R));                      \
            Im[p] = f2fma(DI, R, f2mul(DR, I));                       \
        }                                                             \
    }

// one full layer body (LL = layer index, compile-time).
// No pre-transpose barrier: transpose store slots are self-owned (bijective
// (t,p)->unit map; same thread last read them in the previous perm-load).
// For LAST layer: L_A(LL) scalar dropped (diagonal before |.|^2 measurement).
#define LAYER_BODY(LL, LAST)                                          \
    {                                                                 \
        PACKG((LL) * 12 + 11)                                         \
        REGPG((LL) * 12 + 10, 1)                                      \
        REGPG((LL) * 12 + 9, 2)                                       \
        REGPG((LL) * 12 + 8, 4)                                       \
        SHUFG((LL) * 12 + 7, 1, t & 1)                                \
        SHUFG((LL) * 12 + 6, 2, (t >> 1) & 1)                         \
        SHUFG((LL) * 12 + 5, 4, (t >> 2) & 1)                         \
        SHUFG((LL) * 12 + 4, 8, (t >> 3) & 1)                         \
        _Pragma("unroll")                                             \
        for (int p = 0; p < 8; p++) {                                 \
            exR64[AbU ^ p] = Re[p];                                   \
            exI64[AbU ^ p] = Im[p];                                   \
        }                                                             \
        __syncthreads();                                              \
        _Pragma("unroll")                                             \
        for (int pB = 0; pB < 8; pB++) {                              \
            const int a0 = Bb ^ bmoff(2 * pB);                        \
            const int a1 = Bb ^ bmoff(2 * pB + 1);                    \
            float r0 = *(const float*)((const char*)exR + a0);        \
            float r1 = *(const float*)((const char*)exR + a1);        \
            float i0 = *(const float*)((const char*)exI + a0);        \
            float i1 = *(const float*)((const char*)exI + a1);        \
            Re[pB] = pk(r0, r1);                                      \
            Im[pB] = pk(i0, i1);                                      \
        }                                                             \
        if (!(LAST)) {                                                \
            float2 ts1 = TS1t[(LL) - 1][t];                           \
            APPLY_SCALAR(ts1)                                         \
        }                                                             \
        APPLY_TAB(LP1t, (LL))                                         \
        PACKG((LL) * 12 + 3)                                          \
        REGPG((LL) * 12 + 2, 1)                                       \
        REGPG((LL) * 12 + 1, 2)                                       \
        REGPG((LL) * 12 + 0, 4)                                       \
        if (!(LAST)) {                                                \
            __syncthreads();                                          \
            _Pragma("unroll")                                         \
            for (int pB = 0; pB < 8; pB++) {                          \
                ulonglong2 dd = *(const ulonglong2*)&LP2t[(LL)][pB][0]; \
                u64 DR = dd.x, DI = dd.y, DNI = LP2t[(LL)][pB][2];    \
                u64 R = Re[pB], I = Im[pB];                           \
                u64 Rn = f2fma(DNI, I, f2mul(DR, R));                 \
                u64 In = f2fma(DI, R, f2mul(DR, I));                  \
                float r0, r1, i0v, i1v;                               \
                upk(Rn, r0, r1);                                      \
                upk(In, i0v, i1v);                                    \
                const int a0 = puA ^ laddr(perm12((2 * pB) << 8));    \
                const int a1 = puA ^ laddr(perm12((2 * pB + 1) << 8)); \
                *(float*)((char*)exR + a0) = r0;                      \
                *(float*)((char*)exI + a0) = i0v;                     \
                *(float*)((char*)exR + a1) = r1;                      \
                *(float*)((char*)exI + a1) = i1v;                     \
            }                                                         \
            __syncthreads();                                          \
            _Pragma("unroll")                                         \
            for (int p = 0; p < 8; p++) {                             \
                Re[p] = exR64[AbU ^ p];                               \
                Im[p] = exI64[AbU ^ p];                               \
            }                                                         \
            {                                                         \
                float2 ts2 = TS2t[(LL) + 1][t & 15];                  \
                APPLY_SCALAR(ts2)                                     \
                APPLY_TAB(LPAt, (LL) + 1)                             \
            }                                                         \
        }                                                             \
    }

__global__ __launch_bounds__(THREADS, 2)
void qgen_kernel(const float* __restrict__ noise,
                 const float* __restrict__ W1, const float* __restrict__ b1,
                 const float* __restrict__ W2, const float* __restrict__ b2,
                 const float* __restrict__ W3, const float* __restrict__ b3,
                 const float* __restrict__ W4, const float* __restrict__ b4,
                 float* __restrict__ out)
{
    __shared__ __align__(16) float exR[4096];
    __shared__ __align__(16) float exI[4096];
    __shared__ __align__(16) u64   gpkG[48 * 4];   // RA, RB, RBm, RBpm per gate
    __shared__ float2 s_rho[48];                   // right phase (on bit=1)
    __shared__ float2 s_lam[48];                   // left phase (on bit=1)
    __shared__ __align__(16) u64 LP1t[4][8][4];    // Δ1 local (ρ of B gates)
    __shared__ __align__(16) u64 LP2t[4][8][4];    // L_B local (λ of B gates)
    __shared__ __align__(16) u64 LPAt[4][8][4];    // R_A local (ρ of q11..q8)
    __shared__ float2 TS1t[2][256];                // Δ1 thread part (λ of A gates), l=1,2
    __shared__ float2 TS2t[4][16];                 // R_A thread part (ρ of q7..q4)
    __shared__ float2 s_sc[NPAR];                  // (sin, cos) of 0.5*param
    __shared__ float2 s_v[12][2];
    __shared__ float s_nz[12];
    __shared__ float s_h[64];
    __shared__ float s_meas[12];
    __shared__ float s_wsum[8][12];
    __shared__ float s_h2[64];

    const int t   = threadIdx.x;
    const int bId = blockIdx.x;

    if (t < 12) s_nz[t] = noise[bId * 12 + t];
    __syncthreads();

    // ---- MLP1 ----
    if (t < 64) {
        float acc = b1[t];
        #pragma unroll
        for (int m = 0; m < 12; m++) acc += s_nz[m] * W1[m * 64 + t];
        s_h[t] = tanhf(acc);
    }
    __syncthreads();

    // ---- MLP2 (4-way ILP) + per-param sincos (own value, no extra barrier) ----
    if (t < NPAR) {
        float a0 = b2[t], a1 = 0.f, a2 = 0.f, a3 = 0.f;
        #pragma unroll 4
        for (int j = 0; j < 64; j += 4) {
            a0 += s_h[j + 0] * W2[(j + 0) * NPAR + t];
            a1 += s_h[j + 1] * W2[(j + 1) * NPAR + t];
            a2 += s_h[j + 2] * W2[(j + 2) * NPAR + t];
            a3 += s_h[j + 3] * W2[(j + 3) * NPAR + t];
        }
        float v = (a0 + a1) + (a2 + a3);
        float sv, cv;
        sincosf(0.5f * v, &sv, &cv);
        s_sc[t] = make_float2(sv, cv);
    }
    __syncthreads();

    // ---- per-gate: U = RZ RY RX = [[a,b],[-b*,a*]], a=gx+igy, b=gz+igw.
    // U ~ diag(1, conj(c)conj(d)) * [[ra,rb],[-rb,ra]] * diag(1, d*conj(c))
    if (t < 48) {
        float2 A  = s_sc[t * 3 + 0];
        float2 Bv = s_sc[t * 3 + 1];
        float2 Cv = s_sc[t * 3 + 2];
        float sa = A.x,  ca = A.y;
        float sb = Bv.x, cb = Bv.y;
        float sc = Cv.x, cc = Cv.y;
        float x = cb * ca, y = sb * sa, z = sb * ca, w = cb * sa;
        float gx =  cc * x + sc * y;
        float gy =  cc * y - sc * x;
        float gz = -(cc * z + sc * w);
        float gw =  sc * z - cc * w;

        float ra = sqrtf(gx * gx + gy * gy);
        float rb = sqrtf(gz * gz + gw * gw);
        float cx, cyv, dx, dyv;
        if (ra > 1e-30f) { cx = gx / ra; cyv = gy / ra; } else { cx = 1.f; cyv = 0.f; }
        if (rb > 1e-30f) { dx = gz / rb; dyv = gw / rb; } else { dx = 1.f; dyv = 0.f; }

        s_rho[t] = make_float2(dx * cx + dyv * cyv, dyv * cx - dx * cyv);
        s_lam[t] = make_float2(cx * dx - cyv * dyv, -(cx * dyv + cyv * dx));

        u64* r = gpkG + t * 4;
        r[0] = pk(ra, ra);
        r[1] = pk(rb, rb);
        r[2] = pk(-rb, -rb);
        r[3] = pk(rb, -rb);

        if (t < 12) {
            s_v[t][0] = make_float2(gx, gy);
            s_v[t][1] = make_float2(-gz, gw);
        }
    }
    __syncthreads();

    // ---- build diagonal tables ----
    #pragma unroll
    for (int l = 1; l <= 2; l++) {     // L_A(3) dropped (phase-only before meas)
        float2 acc = make_float2(1.f, 0.f);
        #pragma unroll
        for (int b = 0; b < 8; b++)
            if ((t >> b) & 1) acc = cm2(acc, s_lam[l * 12 + (11 - b)]);
        TS1t[l - 1][t] = acc;
    }
    if (t < 48) {
        int l = (t >> 4) + 1, u = t & 15;
        float2 acc = make_float2(1.f, 0.f);
        #pragma unroll
        for (int j = 0; j < 4; j++)
            if ((u >> j) & 1) acc = cm2(acc, s_rho[l * 12 + (7 - j)]);
        TS2t[l][u] = acc;
    }
    if (t < 24) {
        int l = t / 8 + 1, r = t % 8;
        {
            float2 b0 = make_float2(1.f, 0.f);
            if (r & 1) b0 = cm2(b0, s_rho[l * 12 + 2]);
            if (r & 2) b0 = cm2(b0, s_rho[l * 12 + 1]);
            if (r & 4) b0 = cm2(b0, s_rho[l * 12 + 0]);
            float2 b1v = cm2(b0, s_rho[l * 12 + 3]);
            LP1t[l][r][0] = pk(b0.x, b1v.x);
            LP1t[l][r][1] = pk(b0.y, b1v.y);
            LP1t[l][r][2] = pk(-b0.y, -b1v.y);
        }
        {
            float2 b0 = make_float2(1.f, 0.f);
            if (r & 1) b0 = cm2(b0, s_rho[l * 12 + 10]);
            if (r & 2) b0 = cm2(b0, s_rho[l * 12 + 9]);
            if (r & 4) b0 = cm2(b0, s_rho[l * 12 + 8]);
            float2 b1v = cm2(b0, s_rho[l * 12 + 11]);
            LPAt[l][r][0] = pk(b0.x, b1v.x);
            LPAt[l][r][1] = pk(b0.y, b1v.y);
            LPAt[l][r][2] = pk(-b0.y, -b1v.y);
        }
    }
    if (t < 16) {
        int l = t / 8 + 1, r = t % 8;
        float2 b0 = make_float2(1.f, 0.f);
        if (r & 1) b0 = cm2(b0, s_lam[l * 12 + 2]);
        if (r & 2) b0 = cm2(b0, s_lam[l * 12 + 1]);
        if (r & 4) b0 = cm2(b0, s_lam[l * 12 + 0]);
        float2 b1v = cm2(b0, s_lam[l * 12 + 3]);
        LP2t[l][r][0] = pk(b0.x, b1v.x);
        LP2t[l][r][1] = pk(b0.y, b1v.y);
        LP2t[l][r][2] = pk(-b0.y, -b1v.y);
    }

    // ---- per-thread exchange addresses ----
    const int AbU = ((t >> 1) << 4) | (((t & 1) << 3) ^ ((t >> 1) & 15));
    const int uh  = t >> 5;
    const int Bb  = (uh << 7) | ((((t >> 1) & 15) ^ uh) << 3) | ((t & 1) << 2);
    const int puA = laddr(perm12(t));

    u64* exR64 = (u64*)exR;
    u64* exI64 = (u64*)exI;

    __syncthreads();   // tables + gpkG + s_v visible

    // ---- layer 0 (gates + first ring) via product-state synthesis ----
    u64 Re[8], Im[8];
    {
        c2 v[12][2];
        #pragma unroll
        for (int q = 0; q < 12; q++) {
            float2 a0 = s_v[q][0], a1 = s_v[q][1];
            v[q][0].r = a0.x; v[q][0].i = a0.y;
            v[q][1].r = a1.x; v[q][1].i = a1.y;
        }
        const int x2 = ((t >> 5) ^ (t >> 6)) & 1;
        const int x3 = ((t >> 4) ^ (t >> 5)) & 1;
        const int x4 = ((t >> 3) ^ (t >> 4)) & 1;
        const int x5 = ((t >> 2) ^ (t >> 3)) & 1;
        const int x6 = ((t >> 1) ^ (t >> 2)) & 1;
        const int x7 = ( t       ^ (t >> 1)) & 1;
        const int e0 = (t >> 7) & 1;
        const int e1 = ((t >> 6) ^ (t >> 7)) & 1;
        const int e4 = t & 1;

        c2 base = cmul(cmul(cmul(v[2][x2], v[3][x3]), cmul(v[4][x4], v[5][x5])),
                       cmul(v[6][x6], v[7][x7]));
        c2 base2[2];
        base2[0] = cmul(base, v[8][e4]);
        base2[1] = cmul(base, v[8][e4 ^ 1]);

        c2 A[2];
        A[0] = cmul(v[0][e0],     v[1][e1]);
        A[1] = cmul(v[0][e0 ^ 1], v[1][e1 ^ 1]);
        c2 B[4];
        B[0] = cmul(A[0], v[11][0]);
        B[1] = cmul(A[1], v[11][1]);
        B[2] = cmul(A[0], v[11][1]);
        B[3] = cmul(A[1], v[11][0]);
        c2 C[8];
        #pragma unroll
        for (int k2 = 0; k2 < 2; k2++)
            #pragma unroll
            for (int j = 0; j < 4; j++)
                C[k2 * 4 + j] = cmul(B[j], v[10][((j >> 1) & 1) ^ k2]);
        #pragma unroll
        for (int k3 = 0; k3 < 2; k3++)
            #pragma unroll
            for (int j = 0; j < 8; j += 2) {
                c2 d0 = cmul(cmul(C[j],     v[9][((j >> 2) & 1) ^ k3]), base2[k3]);
                c2 d1 = cmul(cmul(C[j + 1], v[9][(((j+1) >> 2) & 1) ^ k3]), base2[k3]);
                int p = (k3 * 8 + j) >> 1;
                Re[p] = pk(d0.r, d1.r);
                Im[p] = pk(d0.i, d1.i);
            }
    }

    // R_A(1): right phases of layer-1 A gates (post-synthesis, layout A)
    {
        float2 ts2 = TS2t[1][t & 15];
        APPLY_SCALAR(ts2)
        APPLY_TAB(LPAt, 1)
    }

    // ---- layers 1..3 (fully unrolled) ----
    LAYER_BODY(1, false)
    LAYER_BODY(2, false)
    LAYER_BODY(3, true)

    // ---- <Z_q> in layout B with post-ring prefix-parity signs ----
    float T0 = 0.f, T1 = 0.f, T2 = 0.f, T3 = 0.f;
    #pragma unroll
    for (int pB = 0; pB < 8; pB++) {
        u64 p2 = f2fma(Im[pB], Im[pB], f2mul(Re[pB], Re[pB]));
        float pl, ph; upk(p2, pl, ph);
        float sm = pl + ph, df = pl - ph;
        T0 += (__popc(pB & 3) & 1) ? -df : df;
        T1 += (__popc(pB & 6) & 1) ? -sm : sm;
        T2 += (__popc(pB & 7) & 1) ? -sm : sm;
        T3 += (__popc(pB & 7) & 1) ? -df : df;
    }
    float c[12];
    c[0] = (__popc(t) & 1) ? -T0 : T0;
    c[1] = T1; c[2] = T2; c[3] = T3;
    #pragma unroll
    for (int q = 4; q < 12; q++) {
        const int tmask = (0xFF << (11 - q)) & 0xFF;
        c[q] = (__popc(t & tmask) & 1) ? -T3 : T3;
    }

    #pragma unroll
    for (int s = 16; s >= 1; s >>= 1) {
        #pragma unroll
        for (int q = 0; q < 12; q++)
            c[q] += __shfl_xor_sync(0xffffffffu, c[q], s);
    }
    const int warp = t >> 5, lane = t & 31;
    if (lane == 0) {
        #pragma unroll
        for (int q = 0; q < 12; q++) s_wsum[warp][q] = c[q];
    }
    __syncthreads();
    if (t < 12) {
        float m = 0.f;
        #pragma unroll
        for (int w = 0; w < 8; w++) m += s_wsum[w][t];
        s_meas[t] = m;
    }
    __syncthreads();

    // ---- MLP3 ----
    if (t < 64) {
        float acc = b3[t];
        #pragma unroll
        for (int q = 0; q < 12; q++) acc += s_meas[q] * W3[q * 64 + t];
        s_h2[t] = tanhf(acc);
    }
    __syncthreads();

    // ---- out: 32 threads, warp-parallel reduction ----
    if (t < 32) {
        float p0 = s_h2[t] * W4[t * 2 + 0] + s_h2[t + 32] * W4[(t + 32) * 2 + 0];
        float p1 = s_h2[t] * W4[t * 2 + 1] + s_h2[t + 32] * W4[(t + 32) * 2 + 1];
        #pragma unroll
        for (int s = 16; s >= 1; s >>= 1) {
            p0 += __shfl_xor_sync(0xffffffffu, p0, s);
            p1 += __shfl_xor_sync(0xffffffffu, p1, s);
        }
        if (t == 0) {
            out[bId * 2 + 0] = p0 + b4[0];
            out[bId * 2 + 1] = p1 + b4[1];
        }
    }
}

extern "C" void kernel_launch(void* const* d_in, const int* in_sizes, int n_in,
                              void* d_out, int out_size)
{
    (void)n_in; (void)out_size;
    const float* noise = (const float*)d_in[0];
    const float* W1    = (const float*)d_in[1];
    const float* b1    = (const float*)d_in[2];
    const float* W2    = (const float*)d_in[3];
    const float* b2    = (const float*)d_in[4];
    const float* W3    = (const float*)d_in[5];
    const float* b3    = (const float*)d_in[6];
    const float* W4    = (const float*)d_in[7];
    const float* b4    = (const float*)d_in[8];
    float* out = (float*)d_out;

    const int B = in_sizes[0] / NQ;
    qgen_kernel<<<B, THREADS>>>(noise, W1, b1, W2, b2, W3, b3, W4, b4, out);
}

// round 17
// speedup vs baseline: 1.0801x; 1.0351x over previous
#include <cuda_runtime.h>

typedef unsigned long long u64;

#define NQ    12
#define DEPTH 4
#define NPAR  144
#define THREADS 256

// ---------- f32x2 packed helpers ----------
__device__ __forceinline__ u64 f2fma(u64 a, u64 b, u64 c) {
    u64 d; asm("fma.rn.f32x2 %0,%1,%2,%3;" : "=l"(d) : "l"(a), "l"(b), "l"(c)); return d;
}
__device__ __forceinline__ u64 f2mul(u64 a, u64 b) {
    u64 d; asm("mul.rn.f32x2 %0,%1,%2;" : "=l"(d) : "l"(a), "l"(b)); return d;
}
__device__ __forceinline__ u64 pk(float lo, float hi) {
    u64 r; asm("mov.b64 %0,{%1,%2};" : "=l"(r) : "f"(lo), "f"(hi)); return r;
}
__device__ __forceinline__ void upk(u64 v, float& lo, float& hi) {
    asm("mov.b64 {%0,%1},%2;" : "=f"(lo), "=f"(hi) : "l"(v));
}
__device__ __forceinline__ u64 f2swap(u64 v) {
    float lo, hi; upk(v, lo, hi); return pk(hi, lo);
}

struct c2 { float r, i; };
__device__ __forceinline__ c2 cmul(c2 a, c2 b) {
    c2 o; o.r = a.r * b.r - a.i * b.i; o.i = a.r * b.i + a.i * b.r; return o;
}
__device__ __forceinline__ float2 cm2(float2 a, float2 b) {
    return make_float2(a.x * b.x - a.y * b.y, a.x * b.y + a.y * b.x);
}

// ---------- CNOT-ring permutation (reference gate order) ----------
__device__ __forceinline__ int perm12(int s) {
    int d = s;
    #pragma unroll
    for (int q = 0; q < 12; q++) {
        int bc = 11 - q, bt = 11 - ((q + 1) % 12);
        d ^= ((d >> bc) & 1) << bt;
    }
    return d;
}
__device__ __forceinline__ int laddr(int d) {
    return ((d >> 5) << 7) | ((((d >> 1) & 15) ^ ((d >> 5) & 15)) << 3) | ((d & 1) << 2);
}
__device__ __forceinline__ int bmoff(int m) {
    return (m << 10) | ((m & 1) << 6);
}

// ---------- real-core gate macros (G = [[ra, rb],[-rb, ra]]) ----------
#define LOADG(gi)                                                     \
    ulonglong2 g01 = *(const ulonglong2*)(gpkG + (gi) * 4);           \
    ulonglong2 g23 = *(const ulonglong2*)(gpkG + (gi) * 4 + 2);       \
    u64 RA = g01.x, RB = g01.y, RBm = g23.x, RBpm = g23.y;

#define PACKG(gi)                                                     \
    {                                                                 \
        LOADG(gi)                                                     \
        (void)RB; (void)RBm;                                          \
        _Pragma("unroll")                                             \
        for (int p = 0; p < 8; p++) {                                 \
            u64 R = Re[p], I = Im[p];                                 \
            Re[p] = f2fma(RBpm, f2swap(R), f2mul(RA, R));             \
            Im[p] = f2fma(RBpm, f2swap(I), f2mul(RA, I));             \
        }                                                             \
    }

#define REGPG(gi, mask)                                               \
    {                                                                 \
        LOADG(gi)                                                     \
        (void)RBpm;                                                   \
        _Pragma("unroll")                                             \
        for (int p0 = 0; p0 < 8; p0++) {                              \
            if (p0 & (mask)) continue;                                \
            const int p1 = p0 | (mask);                               \
            u64 aR = Re[p0], aI = Im[p0], bR = Re[p1], bI = Im[p1];   \
            Re[p0] = f2fma(RB, bR, f2mul(RA, aR));                    \
            Im[p0] = f2fma(RB, bI, f2mul(RA, aI));                    \
            Re[p1] = f2fma(RBm, aR, f2mul(RA, bR));                   \
            Im[p1] = f2fma(RBm, aI, f2mul(RA, bI));                   \
        }                                                             \
    }

#define SHUFG(gi, lm, mybit)                                          \
    {                                                                 \
        LOADG(gi)                                                     \
        (void)RBpm;                                                   \
        u64 Yo = (mybit) ? RBm : RB;                                  \
        _Pragma("unroll")                                             \
        for (int p = 0; p < 8; p++) {                                 \
            u64 mR = Re[p], mI = Im[p];                               \
            u64 oR = __shfl_xor_sync(0xffffffffu, mR, lm);            \
            u64 oI = __shfl_xor_sync(0xffffffffu, mI, lm);            \
            Re[p] = f2fma(Yo, oR, f2mul(RA, mR));                     \
            Im[p] = f2fma(Yo, oI, f2mul(RA, mI));                     \
        }                                                             \
    }

// diagonal passes
#define APPLY_SCALAR(sv)                                              \
    {                                                                 \
        u64 SX = pk((sv).x, (sv).x);                                  \
        u64 SY = pk((sv).y, (sv).y);                                  \
        u64 SYm = pk(-(sv).y, -(sv).y);                               \
        _Pragma("unroll")                                             \
        for (int p = 0; p < 8; p++) {                                 \
            u64 R = Re[p], I = Im[p];                                 \
            Re[p] = f2fma(SYm, I, f2mul(SX, R));                      \
            Im[p] = f2fma(SY, R, f2mul(SX, I));                       \
        }                                                             \
    }

#define APPLY_TAB(tabname, li)                                        \
    {                                                                 \
        _Pragma("unroll")                                             \
        for (int p = 0; p < 8; p++) {                                 \
            ulonglong2 dd = *(const ulonglong2*)&tabname[li][p][0];   \
            u64 DR = dd.x, DI = dd.y, DNI = tabname[li][p][2];        \
            u64 R = Re[p], I = Im[p];                                 \
            Re[p] = f2fma(DNI, I, f2mul(DR, R));                      \
            Im[p] = f2fma(DI, R, f2mul(DR, I));                       \
        }                                                             \
    }

// one full layer body (LL = layer index, compile-time).
// No pre-transpose barrier: transpose store slots are self-owned (bijective
// (t,p)->unit map; same thread last read them in the previous perm-load).
// For LAST layer: L_A(LL) scalar dropped (diagonal before |.|^2 measurement).
#define LAYER_BODY(LL, LAST)                                          \
    {                                                                 \
        PACKG((LL) * 12 + 11)                                         \
        REGPG((LL) * 12 + 10, 1)                                      \
        REGPG((LL) * 12 + 9, 2)                                       \
        REGPG((LL) * 12 + 8, 4)                                       \
        SHUFG((LL) * 12 + 7, 1, t & 1)                                \
        SHUFG((LL) * 12 + 6, 2, (t >> 1) & 1)                         \
        SHUFG((LL) * 12 + 5, 4, (t >> 2) & 1)                         \
        SHUFG((LL) * 12 + 4, 8, (t >> 3) & 1)                         \
        _Pragma("unroll")                                             \
        for (int p = 0; p < 8; p++) {                                 \
            exR64[AbU ^ p] = Re[p];                                   \
            exI64[AbU ^ p] = Im[p];                                   \
        }                                                             \
        __syncthreads();                                              \
        _Pragma("unroll")                                             \
        for (int pB = 0; pB < 8; pB++) {                              \
            const int a0 = Bb ^ bmoff(2 * pB);                        \
            const int a1 = Bb ^ bmoff(2 * pB + 1);                    \
            float r0 = *(const float*)((const char*)exR + a0);        \
            float r1 = *(const float*)((const char*)exR + a1);        \
            float i0 = *(const float*)((const char*)exI + a0);        \
            float i1 = *(const float*)((const char*)exI + a1);        \
            Re[pB] = pk(r0, r1);                                      \
            Im[pB] = pk(i0, i1);                                      \
        }                                                             \
        if (!(LAST)) {                                                \
            float2 ts1 = TS1t[(LL) - 1][t];                           \
            APPLY_SCALAR(ts1)                                         \
        }                                                             \
        APPLY_TAB(LP1t, (LL))                                         \
        PACKG((LL) * 12 + 3)                                          \
        REGPG((LL) * 12 + 2, 1)                                       \
        REGPG((LL) * 12 + 1, 2)                                       \
        REGPG((LL) * 12 + 0, 4)                                       \
        if (!(LAST)) {                                                \
            __syncthreads();                                          \
            _Pragma("unroll")                                         \
            for (int pB = 0; pB < 8; pB++) {                          \
                ulonglong2 dd = *(const ulonglong2*)&LP2t[(LL)][pB][0]; \
                u64 DR = dd.x, DI = dd.y, DNI = LP2t[(LL)][pB][2];    \
                u64 R = Re[pB], I = Im[pB];                           \
                u64 Rn = f2fma(DNI, I, f2mul(DR, R));                 \
                u64 In = f2fma(DI, R, f2mul(DR, I));                  \
                float r0, r1, i0v, i1v;                               \
                upk(Rn, r0, r1);                                      \
                upk(In, i0v, i1v);                                    \
                const int a0 = puA ^ laddr(perm12((2 * pB) << 8));    \
                const int a1 = puA ^ laddr(perm12((2 * pB + 1) << 8)); \
                *(float*)((char*)exR + a0) = r0;                      \
                *(float*)((char*)exI + a0) = i0v;                     \
                *(float*)((char*)exR + a1) = r1;                      \
                *(float*)((char*)exI + a1) = i1v;                     \
            }                                                         \
            __syncthreads();                                          \
            _Pragma("unroll")                                         \
            for (int p = 0; p < 8; p++) {                             \
                Re[p] = exR64[AbU ^ p];                               \
                Im[p] = exI64[AbU ^ p];                               \
            }                                                         \
            {                                                         \
                float2 ts2 = TS2t[(LL) + 1][t & 15];                  \
                APPLY_SCALAR(ts2)                                     \
                APPLY_TAB(LPAt, (LL) + 1)                             \
            }                                                         \
        }                                                             \
    }

__global__ __launch_bounds__(THREADS, 2)
void qgen_kernel(const float* __restrict__ noise,
                 const float* __restrict__ W1, const float* __restrict__ b1,
                 const float* __restrict__ W2, const float* __restrict__ b2,
                 const float* __restrict__ W3, const float* __restrict__ b3,
                 const float* __restrict__ W4, const float* __restrict__ b4,
                 float* __restrict__ out)
{
    __shared__ __align__(16) float exR[4096];
    __shared__ __align__(16) float exI[4096];
    __shared__ __align__(16) u64   gpkG[48 * 4];   // RA, RB, RBm, RBpm per gate
    __shared__ float2 s_rho[48];                   // right phase (on bit=1)
    __shared__ float2 s_lam[48];                   // left phase (on bit=1)
    __shared__ __align__(16) u64 LP1t[4][8][4];    // Δ1 local (ρ of B gates)
    __shared__ __align__(16) u64 LP2t[4][8][4];    // L_B local (λ of B gates)
    __shared__ __align__(16) u64 LPAt[4][8][4];    // R_A local (ρ of q11..q8)
    __shared__ float2 TS1t[2][256];                // Δ1 thread part (λ of A gates), l=1,2
    __shared__ float2 TS2t[4][16];                 // R_A thread part (ρ of q7..q4)
    __shared__ float2 s_sc[NPAR];                  // (sin, cos) of 0.5*param
    __shared__ float2 s_v[12][2];
    __shared__ float s_h[64];
    __shared__ float s_meas[12];
    __shared__ float s_wsum[8][12];
    __shared__ float s_h2[64];

    const int t   = threadIdx.x;
    const int bId = blockIdx.x;

    // ---- MLP1 (noise read directly from GMEM — 2 cache lines, L1 broadcast) ----
    if (t < 64) {
        const float* nz = noise + bId * 12;
        float acc = b1[t];
        #pragma unroll
        for (int m = 0; m < 12; m++) acc += nz[m] * W1[m * 64 + t];
        s_h[t] = tanhf(acc);
    }
    __syncthreads();

    // ---- MLP2 (4-way ILP) + per-param sincos (own value, no extra barrier) ----
    if (t < NPAR) {
        float a0 = b2[t], a1 = 0.f, a2 = 0.f, a3 = 0.f;
        #pragma unroll 4
        for (int j = 0; j < 64; j += 4) {
            a0 += s_h[j + 0] * W2[(j + 0) * NPAR + t];
            a1 += s_h[j + 1] * W2[(j + 1) * NPAR + t];
            a2 += s_h[j + 2] * W2[(j + 2) * NPAR + t];
            a3 += s_h[j + 3] * W2[(j + 3) * NPAR + t];
        }
        float v = (a0 + a1) + (a2 + a3);
        float sv, cv;
        sincosf(0.5f * v, &sv, &cv);
        s_sc[t] = make_float2(sv, cv);
    }
    __syncthreads();

    // ---- per-gate: U = RZ RY RX = [[a,b],[-b*,a*]], a=gx+igy, b=gz+igw.
    // U ~ diag(1, conj(c)conj(d)) * [[ra,rb],[-rb,ra]] * diag(1, d*conj(c))
    if (t < 48) {
        float2 A  = s_sc[t * 3 + 0];
        float2 Bv = s_sc[t * 3 + 1];
        float2 Cv = s_sc[t * 3 + 2];
        float sa = A.x,  ca = A.y;
        float sb = Bv.x, cb = Bv.y;
        float sc = Cv.x, cc = Cv.y;
        float x = cb * ca, y = sb * sa, z = sb * ca, w = cb * sa;
        float gx =  cc * x + sc * y;
        float gy =  cc * y - sc * x;
        float gz = -(cc * z + sc * w);
        float gw =  sc * z - cc * w;

        float ra = sqrtf(gx * gx + gy * gy);
        float rb = sqrtf(gz * gz + gw * gw);
        float cx, cyv, dx, dyv;
        if (ra > 1e-30f) { cx = gx / ra; cyv = gy / ra; } else { cx = 1.f; cyv = 0.f; }
        if (rb > 1e-30f) { dx = gz / rb; dyv = gw / rb; } else { dx = 1.f; dyv = 0.f; }

        s_rho[t] = make_float2(dx * cx + dyv * cyv, dyv * cx - dx * cyv);
        s_lam[t] = make_float2(cx * dx - cyv * dyv, -(cx * dyv + cyv * dx));

        ulonglong2* r2 = (ulonglong2*)(gpkG + t * 4);
        r2[0] = make_ulonglong2(pk(ra, ra), pk(rb, rb));
        r2[1] = make_ulonglong2(pk(-rb, -rb), pk(rb, -rb));

        if (t < 12) {
            s_v[t][0] = make_float2(gx, gy);
            s_v[t][1] = make_float2(-gz, gw);
        }
    }
    __syncthreads();

    // ---- build diagonal tables (subset threads) + layer-0 synthesis (all
    //      threads) in ONE barrier window — synthesis only needs s_v ----
    #pragma unroll
    for (int l = 1; l <= 2; l++) {     // L_A(3) dropped (phase-only before meas)
        float2 acc = make_float2(1.f, 0.f);
        #pragma unroll
        for (int b = 0; b < 8; b++)
            if ((t >> b) & 1) acc = cm2(acc, s_lam[l * 12 + (11 - b)]);
        TS1t[l - 1][t] = acc;
    }
    if (t < 48) {
        int l = (t >> 4) + 1, u = t & 15;
        float2 acc = make_float2(1.f, 0.f);
        #pragma unroll
        for (int j = 0; j < 4; j++)
            if ((u >> j) & 1) acc = cm2(acc, s_rho[l * 12 + (7 - j)]);
        TS2t[l][u] = acc;
    }
    if (t < 24) {
        int l = t / 8 + 1, r = t % 8;
        {
            float2 b0 = make_float2(1.f, 0.f);
            if (r & 1) b0 = cm2(b0, s_rho[l * 12 + 2]);
            if (r & 2) b0 = cm2(b0, s_rho[l * 12 + 1]);
            if (r & 4) b0 = cm2(b0, s_rho[l * 12 + 0]);
            float2 b1v = cm2(b0, s_rho[l * 12 + 3]);
            LP1t[l][r][0] = pk(b0.x, b1v.x);
            LP1t[l][r][1] = pk(b0.y, b1v.y);
            LP1t[l][r][2] = pk(-b0.y, -b1v.y);
        }
        {
            float2 b0 = make_float2(1.f, 0.f);
            if (r & 1) b0 = cm2(b0, s_rho[l * 12 + 10]);
            if (r & 2) b0 = cm2(b0, s_rho[l * 12 + 9]);
            if (r & 4) b0 = cm2(b0, s_rho[l * 12 + 8]);
            float2 b1v = cm2(b0, s_rho[l * 12 + 11]);
            LPAt[l][r][0] = pk(b0.x, b1v.x);
            LPAt[l][r][1] = pk(b0.y, b1v.y);
            LPAt[l][r][2] = pk(-b0.y, -b1v.y);
        }
    }
    if (t < 16) {
        int l = t / 8 + 1, r = t % 8;
        float2 b0 = make_float2(1.f, 0.f);
        if (r & 1) b0 = cm2(b0, s_lam[l * 12 + 2]);
        if (r & 2) b0 = cm2(b0, s_lam[l * 12 + 1]);
        if (r & 4) b0 = cm2(b0, s_lam[l * 12 + 0]);
        float2 b1v = cm2(b0, s_lam[l * 12 + 3]);
        LP2t[l][r][0] = pk(b0.x, b1v.x);
        LP2t[l][r][1] = pk(b0.y, b1v.y);
        LP2t[l][r][2] = pk(-b0.y, -b1v.y);
    }

    // ---- per-thread exchange addresses ----
    const int AbU = ((t >> 1) << 4) | (((t & 1) << 3) ^ ((t >> 1) & 15));
    const int uh  = t >> 5;
    const int Bb  = (uh << 7) | ((((t >> 1) & 15) ^ uh) << 3) | ((t & 1) << 2);
    const int puA = laddr(perm12(t));

    u64* exR64 = (u64*)exR;
    u64* exI64 = (u64*)exI;

    // ---- layer 0 (gates + first ring) via product-state synthesis ----
    u64 Re[8], Im[8];
    {
        c2 v[12][2];
        #pragma unroll
        for (int q = 0; q < 12; q++) {
            float2 a0 = s_v[q][0], a1 = s_v[q][1];
            v[q][0].r = a0.x; v[q][0].i = a0.y;
            v[q][1].r = a1.x; v[q][1].i = a1.y;
        }
        const int x2 = ((t >> 5) ^ (t >> 6)) & 1;
        const int x3 = ((t >> 4) ^ (t >> 5)) & 1;
        const int x4 = ((t >> 3) ^ (t >> 4)) & 1;
        const int x5 = ((t >> 2) ^ (t >> 3)) & 1;
        const int x6 = ((t >> 1) ^ (t >> 2)) & 1;
        const int x7 = ( t       ^ (t >> 1)) & 1;
        const int e0 = (t >> 7) & 1;
        const int e1 = ((t >> 6) ^ (t >> 7)) & 1;
        const int e4 = t & 1;

        c2 base = cmul(cmul(cmul(v[2][x2], v[3][x3]), cmul(v[4][x4], v[5][x5])),
                       cmul(v[6][x6], v[7][x7]));
        c2 base2[2];
        base2[0] = cmul(base, v[8][e4]);
        base2[1] = cmul(base, v[8][e4 ^ 1]);

        c2 A[2];
        A[0] = cmul(v[0][e0],     v[1][e1]);
        A[1] = cmul(v[0][e0 ^ 1], v[1][e1 ^ 1]);
        c2 B[4];
        B[0] = cmul(A[0], v[11][0]);
        B[1] = cmul(A[1], v[11][1]);
        B[2] = cmul(A[0], v[11][1]);
        B[3] = cmul(A[1], v[11][0]);
        c2 C[8];
        #pragma unroll
        for (int k2 = 0; k2 < 2; k2++)
            #pragma unroll
            for (int j = 0; j < 4; j++)
                C[k2 * 4 + j] = cmul(B[j], v[10][((j >> 1) & 1) ^ k2]);
        #pragma unroll
        for (int k3 = 0; k3 < 2; k3++)
            #pragma unroll
            for (int j = 0; j < 8; j += 2) {
                c2 d0 = cmul(cmul(C[j],     v[9][((j >> 2) & 1) ^ k3]), base2[k3]);
                c2 d1 = cmul(cmul(C[j + 1], v[9][(((j+1) >> 2) & 1) ^ k3]), base2[k3]);
                int p = (k3 * 8 + j) >> 1;
                Re[p] = pk(d0.r, d1.r);
                Im[p] = pk(d0.i, d1.i);
            }
    }
    __syncthreads();   // tables visible (synthesis overlapped with table build)

    // R_A(1): right phases of layer-1 A gates (post-synthesis, layout A)
    {
        float2 ts2 = TS2t[1][t & 15];
        APPLY_SCALAR(ts2)
        APPLY_TAB(LPAt, 1)
    }

    // ---- layers 1..3 (fully unrolled) ----
    LAYER_BODY(1, false)
    LAYER_BODY(2, false)
    LAYER_BODY(3, true)

    // ---- <Z_q> in layout B with post-ring prefix-parity signs ----
    float T0 = 0.f, T1 = 0.f, T2 = 0.f, T3 = 0.f;
    #pragma unroll
    for (int pB = 0; pB < 8; pB++) {
        u64 p2 = f2fma(Im[pB], Im[pB], f2mul(Re[pB], Re[pB]));
        float pl, ph; upk(p2, pl, ph);
        float sm = pl + ph, df = pl - ph;
        T0 += (__popc(pB & 3) & 1) ? -df : df;
        T1 += (__popc(pB & 6) & 1) ? -sm : sm;
        T2 += (__popc(pB & 7) & 1) ? -sm : sm;
        T3 += (__popc(pB & 7) & 1) ? -df : df;
    }
    float c[12];
    c[0] = (__popc(t) & 1) ? -T0 : T0;
    c[1] = T1; c[2] = T2; c[3] = T3;
    #pragma unroll
    for (int q = 4; q < 12; q++) {
        const int tmask = (0xFF << (11 - q)) & 0xFF;
        c[q] = (__popc(t & tmask) & 1) ? -T3 : T3;
    }

    #pragma unroll
    for (int s = 16; s >= 1; s >>= 1) {
        #pragma unroll
        for (int q = 0; q < 12; q++)
            c[q] += __shfl_xor_sync(0xffffffffu, c[q], s);
    }
    const int warp = t >> 5, lane = t & 31;
    if (lane == 0) {
        #pragma unroll
        for (int q = 0; q < 12; q++) s_wsum[warp][q] = c[q];
    }
    __syncthreads();
    if (t < 12) {
        float m = 0.f;
        #pragma unroll
        for (int w = 0; w < 8; w++) m += s_wsum[w][t];
        s_meas[t] = m;
    }
    __syncthreads();

    // ---- MLP3 ----
    if (t < 64) {
        float acc = b3[t];
        #pragma unroll
        for (int q = 0; q < 12; q++) acc += s_meas[q] * W3[q * 64 + t];
        s_h2[t] = tanhf(acc);
    }
    __syncthreads();

    // ---- out: 32 threads, warp-parallel reduction ----
    if (t < 32) {
        float p0 = s_h2[t] * W4[t * 2 + 0] + s_h2[t + 32] * W4[(t + 32) * 2 + 0];
        float p1 = s_h2[t] * W4[t * 2 + 1] + s_h2[t + 32] * W4[(t + 32) * 2 + 1];
        #pragma unroll
        for (int s = 16; s >= 1; s >>= 1) {
            p0 += __shfl_xor_sync(0xffffffffu, p0, s);
            p1 += __shfl_xor_sync(0xffffffffu, p1, s);
        }
        if (t == 0) {
            out[bId * 2 + 0] = p0 + b4[0];
            out[bId * 2 + 1] = p1 + b4[1];
        }
    }
}

extern "C" void kernel_launch(void* const* d_in, const int* in_sizes, int n_in,
                              void* d_out, int out_size)
{
    (void)n_in; (void)out_size;
    const float* noise = (const float*)d_in[0];
    const float* W1    = (const float*)d_in[1];
    const float* b1    = (const float*)d_in[2];
    const float* W2    = (const float*)d_in[3];
    const float* b2    = (const float*)d_in[4];
    const float* W3    = (const float*)d_in[5];
    const float* b3    = (const float*)d_in[6];
    const float* W4    = (const float*)d_in[7];
    const float* b4    = (const float*)d_in[8];
    float* out = (float*)d_out;

    const int B = in_sizes[0] / NQ;
    qgen_kernel<<<B, THREADS>>>(noise, W1, b1, W2, b2, W3, b3, W4, b4, out);
}